// round 3
// baseline (speedup 1.0000x reference)
#include <cuda_runtime.h>
#include <math.h>

#define B_ 4
#define T_ 2048
#define D_ 1024
#define H_ 16
#define DH_ 64

// Scratch (device globals: no allocations allowed)
__device__ float g_qkv[(size_t)B_ * T_ * 3 * D_];   // 96 MB
__device__ float g_attn[(size_t)B_ * T_ * D_];      // 32 MB

// ---------------------------------------------------------------------------
// SGEMM: C[M,N] = A[M,K] @ B[K,N] + bias[N]
// 128x128 block tile, BK=8, 256 threads, 8x8 microtile, float4 everywhere.
// Register-prefetch double buffering on the global->smem path.
// M,N multiples of 128; K multiple of 8 (holds for all three calls).
// ---------------------------------------------------------------------------
__global__ __launch_bounds__(256) void sgemm_bias(
    const float* __restrict__ A, const float* __restrict__ Bm,
    const float* __restrict__ bias, float* __restrict__ C,
    int M, int N, int K)
{
    __shared__ float As[8][132];   // [k][m], padded
    __shared__ float Bs[8][128];   // [k][n]

    const int tid  = threadIdx.x;
    const int bm   = blockIdx.y * 128;
    const int bn   = blockIdx.x * 128;
    const int arow = tid >> 1;
    const int acol = (tid & 1) << 2;
    const int brow = tid >> 5;
    const int bcol = (tid & 31) << 2;
    const int tx   = tid & 15;
    const int ty   = tid >> 4;

    const float* Ap = A + (size_t)(bm + arow) * K + acol;
    const float* Bp = Bm + (size_t)brow * N + bn + bcol;

    float acc[8][8];
#pragma unroll
    for (int i = 0; i < 8; i++)
#pragma unroll
        for (int j = 0; j < 8; j++) acc[i][j] = 0.f;

    // prefetch first tile
    float4 av = *(const float4*)(Ap);
    float4 bv = *(const float4*)(Bp);

    for (int k0 = 0; k0 < K; k0 += 8) {
        As[acol + 0][arow] = av.x;
        As[acol + 1][arow] = av.y;
        As[acol + 2][arow] = av.z;
        As[acol + 3][arow] = av.w;
        *(float4*)&Bs[brow][bcol] = bv;
        __syncthreads();

        // prefetch next tile while computing this one
        if (k0 + 8 < K) {
            av = *(const float4*)(Ap + k0 + 8);
            bv = *(const float4*)(Bp + (size_t)(k0 + 8) * N);
        }

#pragma unroll
        for (int k = 0; k < 8; k++) {
            float ra[8], rb[8];
            *(float4*)(ra + 0) = *(const float4*)&As[k][ty * 8 + 0];
            *(float4*)(ra + 4) = *(const float4*)&As[k][ty * 8 + 4];
            *(float4*)(rb + 0) = *(const float4*)&Bs[k][tx * 8 + 0];
            *(float4*)(rb + 4) = *(const float4*)&Bs[k][tx * 8 + 4];
#pragma unroll
            for (int i = 0; i < 8; i++)
#pragma unroll
                for (int j = 0; j < 8; j++)
                    acc[i][j] += ra[i] * rb[j];
        }
        __syncthreads();
    }

#pragma unroll
    for (int i = 0; i < 8; i++) {
        const int row = bm + ty * 8 + i;
        float* Cp = C + (size_t)row * N + bn + tx * 8;
        const float* bp = bias + bn + tx * 8;
#pragma unroll
        for (int j4 = 0; j4 < 8; j4 += 4) {
            float4 bvv = *(const float4*)(bp + j4);
            float4 ov;
            ov.x = acc[i][j4 + 0] + bvv.x;
            ov.y = acc[i][j4 + 1] + bvv.y;
            ov.z = acc[i][j4 + 2] + bvv.z;
            ov.w = acc[i][j4 + 3] + bvv.w;
            *(float4*)(Cp + j4) = ov;
        }
    }
}

// ---------------------------------------------------------------------------
// Flash attention, fp32. One block = one (b,h) x 64 query rows.
// qkv layout: [B*T, 3*D] with q at [h*64], k at [D + h*64], v at [2D + h*64].
// Online softmax with running (m,l). Mask==0 -> score=-1000 (matches ref:
// exp(-1000 - m) underflows to 0 when any real score exists; uniform if all
// masked — identical to jax softmax of all -1000).
// ---------------------------------------------------------------------------
__global__ __launch_bounds__(256) void attn_kernel(
    const float* __restrict__ qkv, const int* __restrict__ mask,
    float* __restrict__ out)
{
    __shared__ float Qt[64][64];   // [d][m], pre-scaled by 1/8
    __shared__ float KP[64][64];   // K^T [d][n], reused as P [m][n]
    __shared__ float Vs[64][64];   // [n][d]

    const int tid = threadIdx.x;
    const int tx  = tid & 15;
    const int ty  = tid >> 4;
    const int bh  = blockIdx.y;
    const int b   = bh >> 4;        // / H_
    const int h   = bh & 15;        // % H_
    const int q0  = blockIdx.x << 6;

    const int* mrow = mask + b * T_;
    const size_t rs = 3 * D_;
    const float* base = qkv + (size_t)(b * T_) * rs + h * DH_;

    // Load Q transposed, scaled by 1/sqrt(DH)=0.125
    for (int idx = tid; idx < 64 * 64; idx += 256) {
        int m = idx >> 6, d = idx & 63;
        Qt[d][m] = base[(size_t)(q0 + m) * rs + d] * 0.125f;
    }

    float o[4][4];
    float mrun[4], lrun[4];
#pragma unroll
    for (int i = 0; i < 4; i++) {
        mrun[i] = -1e30f; lrun[i] = 0.f;
#pragma unroll
        for (int j = 0; j < 4; j++) o[i][j] = 0.f;
    }

    for (int key0 = 0; key0 < T_; key0 += 64) {
        __syncthreads();  // protect prior tile's P/V reads
        for (int idx = tid; idx < 64 * 64; idx += 256) {
            int n = idx >> 6, d = idx & 63;
            const float* kvp = base + (size_t)(key0 + n) * rs + d;
            KP[d][n] = kvp[D_];
            Vs[n][d] = kvp[2 * D_];
        }
        __syncthreads();

        // S = Q K^T (already scaled via Q)
        float s[4][4];
#pragma unroll
        for (int i = 0; i < 4; i++)
#pragma unroll
            for (int j = 0; j < 4; j++) s[i][j] = 0.f;

#pragma unroll 4
        for (int d = 0; d < 64; d++) {
            float fq[4], fk[4];
            *(float4*)fq = *(const float4*)&Qt[d][ty * 4];
            *(float4*)fk = *(const float4*)&KP[d][tx * 4];
#pragma unroll
            for (int i = 0; i < 4; i++)
#pragma unroll
                for (int j = 0; j < 4; j++)
                    s[i][j] += fq[i] * fk[j];
        }

        // mask
        int mk[4];
#pragma unroll
        for (int j = 0; j < 4; j++) mk[j] = mrow[key0 + tx * 4 + j];
#pragma unroll
        for (int i = 0; i < 4; i++)
#pragma unroll
            for (int j = 0; j < 4; j++)
                if (mk[j] == 0) s[i][j] = -1000.f;

        // row max across this thread's 4 cols, then across the 16 tx lanes
        float tmax[4];
#pragma unroll
        for (int i = 0; i < 4; i++) {
            tmax[i] = fmaxf(fmaxf(s[i][0], s[i][1]), fmaxf(s[i][2], s[i][3]));
#pragma unroll
            for (int off = 8; off >= 1; off >>= 1)
                tmax[i] = fmaxf(tmax[i], __shfl_xor_sync(0xffffffffu, tmax[i], off));
        }

        float p[4][4], alpha[4], rsum[4];
#pragma unroll
        for (int i = 0; i < 4; i++) {
            float mnew = fmaxf(mrun[i], tmax[i]);
            alpha[i] = __expf(mrun[i] - mnew);
            mrun[i] = mnew;
            float rs4 = 0.f;
#pragma unroll
            for (int j = 0; j < 4; j++) {
                p[i][j] = __expf(s[i][j] - mnew);
                rs4 += p[i][j];
            }
#pragma unroll
            for (int off = 8; off >= 1; off >>= 1)
                rs4 += __shfl_xor_sync(0xffffffffu, rs4, off);
            rsum[i] = rs4;
            lrun[i] = lrun[i] * alpha[i] + rsum[i];
#pragma unroll
            for (int j = 0; j < 4; j++) o[i][j] *= alpha[i];
        }

        __syncthreads();  // all S reads of KP done; reuse as P [m][n]
        float* Ps = &KP[0][0];
#pragma unroll
        for (int i = 0; i < 4; i++)
#pragma unroll
            for (int j = 0; j < 4; j++)
                Ps[(ty * 4 + i) * 64 + tx * 4 + j] = p[i][j];
        __syncthreads();

        // O += P @ V
#pragma unroll 2
        for (int n0 = 0; n0 < 64; n0 += 4) {
            float pr[4][4], vr[4][4];
#pragma unroll
            for (int i = 0; i < 4; i++)
                *(float4*)pr[i] = *(const float4*)&Ps[(ty * 4 + i) * 64 + n0];
#pragma unroll
            for (int nn = 0; nn < 4; nn++)
                *(float4*)vr[nn] = *(const float4*)&Vs[n0 + nn][tx * 4];
#pragma unroll
            for (int nn = 0; nn < 4; nn++)
#pragma unroll
                for (int i = 0; i < 4; i++)
#pragma unroll
                    for (int j = 0; j < 4; j++)
                        o[i][j] += pr[i][nn] * vr[nn][j];
        }
    }

    // finalize: divide by l, write to [B,T,D] merged-head layout
#pragma unroll
    for (int i = 0; i < 4; i++) {
        float inv = 1.f / lrun[i];
        float4 ov;
        ov.x = o[i][0] * inv;
        ov.y = o[i][1] * inv;
        ov.z = o[i][2] * inv;
        ov.w = o[i][3] * inv;
        float* op = out + (size_t)(b * T_ + q0 + ty * 4 + i) * D_ + h * DH_ + tx * 4;
        *(float4*)op = ov;
    }
}

// ---------------------------------------------------------------------------
extern "C" void kernel_launch(void* const* d_in, const int* in_sizes, int n_in,
                              void* d_out, int out_size)
{
    (void)in_sizes; (void)n_in; (void)out_size;
    const float* x     = (const float*)d_in[0];
    const int*   mask  = (const int*)  d_in[1];
    const float* Wqkv  = (const float*)d_in[2];
    const float* bqkv  = (const float*)d_in[3];
    const float* Wout  = (const float*)d_in[4];
    const float* bout  = (const float*)d_in[5];
    float* out = (float*)d_out;

    float* qkv = nullptr;
    float* attn = nullptr;
    cudaGetSymbolAddress((void**)&qkv,  g_qkv);
    cudaGetSymbolAddress((void**)&attn, g_attn);

    // 1) QKV projection: [8192,1024] @ [1024,3072] + b
    dim3 g1((3 * D_) / 128, (B_ * T_) / 128);   // (24, 64)
    sgemm_bias<<<g1, 256>>>(x, Wqkv, bqkv, qkv, B_ * T_, 3 * D_, D_);

    // 2) Attention
    dim3 ga(T_ / 64, B_ * H_);                   // (32, 64)
    attn_kernel<<<ga, 256>>>(qkv, mask, attn);

    // 3) Output projection: [8192,1024] @ [1024,1024] + b
    dim3 g2(D_ / 128, (B_ * T_) / 128);          // (8, 64)
    sgemm_bias<<<g2, 256>>>(attn, Wout, bout, out, B_ * T_, D_, D_);
}

// round 6
// speedup vs baseline: 1.2323x; 1.2323x over previous
#include <cuda_runtime.h>
#include <cuda_bf16.h>
#include <cstdint>
#include <math.h>

#define B_ 4
#define T_ 2048
#define D_ 1024
#define H_ 16
#define DH_ 64
#define M_ (B_ * T_)        // 8192

// ---------------- scratch (device globals; no allocs allowed) --------------
__device__ float g_qkv[(size_t)M_ * 3 * D_];                 // 96 MB
__device__ float g_attn[(size_t)M_ * D_];                    // 32 MB
__device__ __nv_bfloat16 g_xhi[(size_t)M_ * D_];             // 16 MB
__device__ __nv_bfloat16 g_xlo[(size_t)M_ * D_];
__device__ __nv_bfloat16 g_ahi[(size_t)M_ * D_];
__device__ __nv_bfloat16 g_alo[(size_t)M_ * D_];
__device__ __nv_bfloat16 g_wqkvT_hi[(size_t)3 * D_ * D_];    // 6 MB
__device__ __nv_bfloat16 g_wqkvT_lo[(size_t)3 * D_ * D_];
__device__ __nv_bfloat16 g_woutT_hi[(size_t)D_ * D_];        // 2 MB
__device__ __nv_bfloat16 g_woutT_lo[(size_t)D_ * D_];

// ---------------- helpers ---------------------------------------------------
__device__ __forceinline__ uint32_t smem_u32(const void* p) {
    uint32_t a;
    asm("{ .reg .u64 t; cvta.to.shared.u64 t, %1; cvt.u32.u64 %0, t; }"
        : "=r"(a) : "l"(p));
    return a;
}
__device__ __forceinline__ void cp16(uint32_t dst, const void* src) {
    asm volatile("cp.async.cg.shared.global [%0], [%1], 16;"
                 :: "r"(dst), "l"(src) : "memory");
}
#define CP_COMMIT()  asm volatile("cp.async.commit_group;" ::: "memory")
#define CP_WAIT1()   asm volatile("cp.async.wait_group 1;" ::: "memory")
#define CP_WAIT0()   asm volatile("cp.async.wait_group 0;" ::: "memory")

#define LDSM4(r, addr) \
    asm volatile("ldmatrix.sync.aligned.m8n8.x4.shared.b16 {%0,%1,%2,%3}, [%4];" \
                 : "=r"((r)[0]), "=r"((r)[1]), "=r"((r)[2]), "=r"((r)[3]) : "r"(addr))
// B stored [N][K] row-major -> NON-trans x2 gives the .col B fragment
#define LDSM2(r, addr) \
    asm volatile("ldmatrix.sync.aligned.m8n8.x2.shared.b16 {%0,%1}, [%2];" \
                 : "=r"((r)[0]), "=r"((r)[1]) : "r"(addr))
#define MMA16816(c, a, bb) \
    asm volatile("mma.sync.aligned.m16n8k16.row.col.f32.bf16.bf16.f32 " \
                 "{%0,%1,%2,%3}, {%4,%5,%6,%7}, {%8,%9}, {%0,%1,%2,%3};" \
                 : "+f"((c)[0]), "+f"((c)[1]), "+f"((c)[2]), "+f"((c)[3]) \
                 : "r"((a)[0]), "r"((a)[1]), "r"((a)[2]), "r"((a)[3]), \
                   "r"((bb)[0]), "r"((bb)[1]))

// ---------------------------------------------------------------------------
// Split fp32 -> bf16 hi/lo (vectorized by 4)
// ---------------------------------------------------------------------------
__global__ __launch_bounds__(256) void split_f32(
    const float4* __restrict__ in, __nv_bfloat162* __restrict__ hi,
    __nv_bfloat162* __restrict__ lo, int n4)
{
    int i = blockIdx.x * 256 + threadIdx.x;
    if (i >= n4) return;
    float4 v = in[i];
    __nv_bfloat16 h0 = __float2bfloat16(v.x);
    __nv_bfloat16 h1 = __float2bfloat16(v.y);
    __nv_bfloat16 h2 = __float2bfloat16(v.z);
    __nv_bfloat16 h3 = __float2bfloat16(v.w);
    hi[2 * i + 0] = __halves2bfloat162(h0, h1);
    hi[2 * i + 1] = __halves2bfloat162(h2, h3);
    lo[2 * i + 0] = __halves2bfloat162(
        __float2bfloat16(v.x - __bfloat162float(h0)),
        __float2bfloat16(v.y - __bfloat162float(h1)));
    lo[2 * i + 1] = __halves2bfloat162(
        __float2bfloat16(v.z - __bfloat162float(h2)),
        __float2bfloat16(v.w - __bfloat162float(h3)));
}

// ---------------------------------------------------------------------------
// Transpose W[K][N] -> Wt[N][K] with bf16 hi/lo split
// ---------------------------------------------------------------------------
__global__ void transpose_split(
    const float* __restrict__ W, __nv_bfloat16* __restrict__ hi,
    __nv_bfloat16* __restrict__ lo, int K, int N)
{
    __shared__ float t[32][33];
    const int n0 = blockIdx.x * 32, k0 = blockIdx.y * 32;
    const int tx = threadIdx.x, ty = threadIdx.y;
#pragma unroll
    for (int j = 0; j < 32; j += 8)
        t[ty + j][tx] = W[(size_t)(k0 + ty + j) * N + n0 + tx];
    __syncthreads();
#pragma unroll
    for (int j = 0; j < 32; j += 8) {
        float v = t[tx][ty + j];
        size_t o = (size_t)(n0 + ty + j) * K + k0 + tx;
        __nv_bfloat16 h = __float2bfloat16(v);
        hi[o] = h;
        lo[o] = __float2bfloat16(v - __bfloat162float(h));
    }
}

// ---------------------------------------------------------------------------
// mma.sync bf16-split GEMM: C[M,N] = A[M,K] x Bt[N,K]^T + bias
// 128x128 CTA tile, BK=32, 8 warps (64x32 warp tiles), cp.async 2-stage,
// 3-term split (hi*hi + hi*lo + lo*hi), fp32 accumulate.
// Smem rows padded to 40 bf16 (80B) -> ldmatrix conflict-free.
// ---------------------------------------------------------------------------
#define GTILE 10240u                 // 128 rows * 80 B
#define GSTAGE (4u * GTILE)          // Ahi, Alo, Bhi, Blo
#define GSMEM (2u * GSTAGE)          // 81920 B

__global__ __launch_bounds__(256) void gemm_bf16split_mma(
    const __nv_bfloat16* __restrict__ Ahi, const __nv_bfloat16* __restrict__ Alo,
    const __nv_bfloat16* __restrict__ Bhi, const __nv_bfloat16* __restrict__ Blo,
    const float* __restrict__ bias, float* __restrict__ C,
    int M, int N, int K)
{
    extern __shared__ char smem[];
    const int tid = threadIdx.x;
    const int wid = tid >> 5;
    const int lid = tid & 31;
    const int bm = blockIdx.y * 128;
    const int bn = blockIdx.x * 128;
    const int wm = (wid >> 2) * 64;      // 0 / 64
    const int wn = (wid & 3) * 32;       // 0..96
    const uint32_t sbase = smem_u32(smem);

    float acc[4][4][4];
#pragma unroll
    for (int i = 0; i < 4; i++)
#pragma unroll
        for (int j = 0; j < 4; j++)
#pragma unroll
            for (int c = 0; c < 4; c++) acc[i][j][c] = 0.f;

    const __nv_bfloat16* srcs[4] = {
        Ahi + (size_t)bm * K, Alo + (size_t)bm * K,
        Bhi + (size_t)bn * K, Blo + (size_t)bn * K };

    // fragment base offsets (bytes within a tile)
    const uint32_t aRow = (uint32_t)(wm + (lid & 15)) * 80u;
    const uint32_t aCol = (uint32_t)(lid >> 4) * 16u;
    const uint32_t bRow = (uint32_t)(wn + (lid & 7)) * 80u;
    const uint32_t bCol = (uint32_t)((lid >> 3) & 1) * 16u;

    const int NIT = K >> 5;   // K/32

    // prologue: stage 0
    {
#pragma unroll
        for (int t = 0; t < 8; t++) {
            int idx = tid + (t << 8);
            int tile = idx >> 9, c = idx & 511, row = c >> 2, off = c & 3;
            uint32_t dst = sbase + (uint32_t)tile * GTILE + (uint32_t)row * 80u + (uint32_t)off * 16u;
            cp16(dst, srcs[tile] + (size_t)row * K + off * 8);
        }
        CP_COMMIT();
    }

    for (int it = 0; it < NIT; it++) {
        const uint32_t s = (uint32_t)(it & 1);
        if (it + 1 < NIT) {
            const int k0 = (it + 1) << 5;
            const uint32_t sn = (uint32_t)((it + 1) & 1);
#pragma unroll
            for (int t = 0; t < 8; t++) {
                int idx = tid + (t << 8);
                int tile = idx >> 9, c = idx & 511, row = c >> 2, off = c & 3;
                uint32_t dst = sbase + sn * GSTAGE + (uint32_t)tile * GTILE
                             + (uint32_t)row * 80u + (uint32_t)off * 16u;
                cp16(dst, srcs[tile] + (size_t)row * K + k0 + off * 8);
            }
            CP_COMMIT();
            CP_WAIT1();
        } else {
            CP_WAIT0();
        }
        __syncthreads();

        const uint32_t tb = sbase + s * GSTAGE;
#pragma unroll
        for (int kk = 0; kk < 32; kk += 16) {
            uint32_t ah[4][4], al[4][4], bh[4][2], bl[4][2];
            const uint32_t ac = (uint32_t)kk * 2u + aCol;
            const uint32_t bc = (uint32_t)kk * 2u + bCol;
#pragma unroll
            for (int mt = 0; mt < 4; mt++) {
                uint32_t ad = tb + aRow + (uint32_t)mt * 1280u + ac;
                LDSM4(ah[mt], ad);
                LDSM4(al[mt], ad + GTILE);
            }
#pragma unroll
            for (int nt = 0; nt < 4; nt++) {
                uint32_t bd = tb + 2u * GTILE + bRow + (uint32_t)nt * 640u + bc;
                LDSM2(bh[nt], bd);
                LDSM2(bl[nt], bd + GTILE);
            }
#pragma unroll
            for (int mt = 0; mt < 4; mt++)
#pragma unroll
                for (int nt = 0; nt < 4; nt++) {
                    MMA16816(acc[mt][nt], ah[mt], bh[nt]);
                    MMA16816(acc[mt][nt], ah[mt], bl[nt]);
                    MMA16816(acc[mt][nt], al[mt], bh[nt]);
                }
        }
        __syncthreads();
    }

    // epilogue
    const int gr = lid >> 2;
    const int gc = (lid & 3) * 2;
#pragma unroll
    for (int mt = 0; mt < 4; mt++) {
#pragma unroll
        for (int nt = 0; nt < 4; nt++) {
            const int row = bm + wm + mt * 16 + gr;
            const int col = bn + wn + nt * 8 + gc;
            const float b0 = bias[col], b1 = bias[col + 1];
            float2 v0, v1;
            v0.x = acc[mt][nt][0] + b0; v0.y = acc[mt][nt][1] + b1;
            v1.x = acc[mt][nt][2] + b0; v1.y = acc[mt][nt][3] + b1;
            *(float2*)&C[(size_t)row * N + col] = v0;
            *(float2*)&C[(size_t)(row + 8) * N + col] = v1;
        }
    }
}

// ---------------------------------------------------------------------------
// Flash attention, fp32 SIMT (round-3 passing version, unchanged)
// ---------------------------------------------------------------------------
__global__ __launch_bounds__(256) void attn_kernel(
    const float* __restrict__ qkv, const int* __restrict__ mask,
    float* __restrict__ out)
{
    __shared__ float Qt[64][64];
    __shared__ float KP[64][64];
    __shared__ float Vs[64][64];

    const int tid = threadIdx.x;
    const int tx  = tid & 15;
    const int ty  = tid >> 4;
    const int bh  = blockIdx.y;
    const int b   = bh >> 4;
    const int h   = bh & 15;
    const int q0  = blockIdx.x << 6;

    const int* mrow = mask + b * T_;
    const size_t rs = 3 * D_;
    const float* base = qkv + (size_t)(b * T_) * rs + h * DH_;

    for (int idx = tid; idx < 64 * 64; idx += 256) {
        int m = idx >> 6, d = idx & 63;
        Qt[d][m] = base[(size_t)(q0 + m) * rs + d] * 0.125f;
    }

    float o[4][4];
    float mrun[4], lrun[4];
#pragma unroll
    for (int i = 0; i < 4; i++) {
        mrun[i] = -1e30f; lrun[i] = 0.f;
#pragma unroll
        for (int j = 0; j < 4; j++) o[i][j] = 0.f;
    }

    for (int key0 = 0; key0 < T_; key0 += 64) {
        __syncthreads();
        for (int idx = tid; idx < 64 * 64; idx += 256) {
            int n = idx >> 6, d = idx & 63;
            const float* kvp = base + (size_t)(key0 + n) * rs + d;
            KP[d][n] = kvp[D_];
            Vs[n][d] = kvp[2 * D_];
        }
        __syncthreads();

        float s[4][4];
#pragma unroll
        for (int i = 0; i < 4; i++)
#pragma unroll
            for (int j = 0; j < 4; j++) s[i][j] = 0.f;

#pragma unroll 4
        for (int d = 0; d < 64; d++) {
            float fq[4], fk[4];
            *(float4*)fq = *(const float4*)&Qt[d][ty * 4];
            *(float4*)fk = *(const float4*)&KP[d][tx * 4];
#pragma unroll
            for (int i = 0; i < 4; i++)
#pragma unroll
                for (int j = 0; j < 4; j++)
                    s[i][j] += fq[i] * fk[j];
        }

        int mk[4];
#pragma unroll
        for (int j = 0; j < 4; j++) mk[j] = mrow[key0 + tx * 4 + j];
#pragma unroll
        for (int i = 0; i < 4; i++)
#pragma unroll
            for (int j = 0; j < 4; j++)
                if (mk[j] == 0) s[i][j] = -1000.f;

        float tmax[4];
#pragma unroll
        for (int i = 0; i < 4; i++) {
            tmax[i] = fmaxf(fmaxf(s[i][0], s[i][1]), fmaxf(s[i][2], s[i][3]));
#pragma unroll
            for (int off = 8; off >= 1; off >>= 1)
                tmax[i] = fmaxf(tmax[i], __shfl_xor_sync(0xffffffffu, tmax[i], off));
        }

        float p[4][4], alpha[4];
#pragma unroll
        for (int i = 0; i < 4; i++) {
            float mnew = fmaxf(mrun[i], tmax[i]);
            alpha[i] = __expf(mrun[i] - mnew);
            mrun[i] = mnew;
            float rs4 = 0.f;
#pragma unroll
            for (int j = 0; j < 4; j++) {
                p[i][j] = __expf(s[i][j] - mnew);
                rs4 += p[i][j];
            }
#pragma unroll
            for (int off = 8; off >= 1; off >>= 1)
                rs4 += __shfl_xor_sync(0xffffffffu, rs4, off);
            lrun[i] = lrun[i] * alpha[i] + rs4;
#pragma unroll
            for (int j = 0; j < 4; j++) o[i][j] *= alpha[i];
        }

        __syncthreads();
        float* Ps = &KP[0][0];
#pragma unroll
        for (int i = 0; i < 4; i++)
#pragma unroll
            for (int j = 0; j < 4; j++)
                Ps[(ty * 4 + i) * 64 + tx * 4 + j] = p[i][j];
        __syncthreads();

#pragma unroll 2
        for (int n0 = 0; n0 < 64; n0 += 4) {
            float pr[4][4], vr[4][4];
#pragma unroll
            for (int i = 0; i < 4; i++)
                *(float4*)pr[i] = *(const float4*)&Ps[(ty * 4 + i) * 64 + n0];
#pragma unroll
            for (int nn = 0; nn < 4; nn++)
                *(float4*)vr[nn] = *(const float4*)&Vs[n0 + nn][tx * 4];
#pragma unroll
            for (int nn = 0; nn < 4; nn++)
#pragma unroll
                for (int i = 0; i < 4; i++)
#pragma unroll
                    for (int j = 0; j < 4; j++)
                        o[i][j] += pr[i][nn] * vr[nn][j];
        }
    }

#pragma unroll
    for (int i = 0; i < 4; i++) {
        float inv = 1.f / lrun[i];
        float4 ov;
        ov.x = o[i][0] * inv;
        ov.y = o[i][1] * inv;
        ov.z = o[i][2] * inv;
        ov.w = o[i][3] * inv;
        float* op = out + (size_t)(b * T_ + q0 + ty * 4 + i) * D_ + h * DH_ + tx * 4;
        *(float4*)op = ov;
    }
}

// ---------------------------------------------------------------------------
extern "C" void kernel_launch(void* const* d_in, const int* in_sizes, int n_in,
                              void* d_out, int out_size)
{
    (void)in_sizes; (void)n_in; (void)out_size;
    const float* x     = (const float*)d_in[0];
    const int*   mask  = (const int*)  d_in[1];
    const float* Wqkv  = (const float*)d_in[2];
    const float* bqkv  = (const float*)d_in[3];
    const float* Wout  = (const float*)d_in[4];
    const float* bout  = (const float*)d_in[5];
    float* out = (float*)d_out;

    float *qkv, *attn;
    __nv_bfloat16 *xhi, *xlo, *ahi, *alo, *wqh, *wql, *woh, *wol;
    cudaGetSymbolAddress((void**)&qkv,  g_qkv);
    cudaGetSymbolAddress((void**)&attn, g_attn);
    cudaGetSymbolAddress((void**)&xhi,  g_xhi);
    cudaGetSymbolAddress((void**)&xlo,  g_xlo);
    cudaGetSymbolAddress((void**)&ahi,  g_ahi);
    cudaGetSymbolAddress((void**)&alo,  g_alo);
    cudaGetSymbolAddress((void**)&wqh,  g_wqkvT_hi);
    cudaGetSymbolAddress((void**)&wql,  g_wqkvT_lo);
    cudaGetSymbolAddress((void**)&woh,  g_woutT_hi);
    cudaGetSymbolAddress((void**)&wol,  g_woutT_lo);

    cudaFuncSetAttribute(gemm_bf16split_mma,
                         cudaFuncAttributeMaxDynamicSharedMemorySize, GSMEM);

    // split x -> bf16 hi/lo
    {
        int n4 = (M_ * D_) / 4;
        split_f32<<<(n4 + 255) / 256, 256>>>((const float4*)x,
            (__nv_bfloat162*)xhi, (__nv_bfloat162*)xlo, n4);
    }
    // transpose+split weights
    transpose_split<<<dim3((3 * D_) / 32, D_ / 32), dim3(32, 8)>>>(Wqkv, wqh, wql, D_, 3 * D_);
    transpose_split<<<dim3(D_ / 32, D_ / 32), dim3(32, 8)>>>(Wout, woh, wol, D_, D_);

    // QKV projection
    gemm_bf16split_mma<<<dim3((3 * D_) / 128, M_ / 128), 256, GSMEM>>>(
        xhi, xlo, wqh, wql, bqkv, qkv, M_, 3 * D_, D_);

    // attention
    attn_kernel<<<dim3(T_ / 64, B_ * H_), 256>>>(qkv, mask, attn);

    // split attention output
    {
        int n4 = (M_ * D_) / 4;
        split_f32<<<(n4 + 255) / 256, 256>>>((const float4*)attn,
            (__nv_bfloat162*)ahi, (__nv_bfloat162*)alo, n4);
    }
    // output projection
    gemm_bf16split_mma<<<dim3(D_ / 128, M_ / 128), 256, GSMEM>>>(
        ahi, alo, woh, wol, bout, out, M_, D_, D_);
}

// round 16
// speedup vs baseline: 3.4396x; 2.7912x over previous
#include <cuda_runtime.h>
#include <cuda_bf16.h>
#include <cstdint>
#include <math.h>

#define B_ 4
#define T_ 2048
#define D_ 1024
#define H_ 16
#define DH_ 64
#define M_ (B_ * T_)        // 8192

// ---------------- scratch (device globals; no allocs allowed) --------------
__device__ __nv_bfloat16 g_qkvhi[(size_t)M_ * 3 * D_];       // 48 MB
__device__ __nv_bfloat16 g_qkvlo[(size_t)M_ * 3 * D_];       // 48 MB
__device__ __nv_bfloat16 g_xhi[(size_t)M_ * D_];             // 16 MB
__device__ __nv_bfloat16 g_xlo[(size_t)M_ * D_];
__device__ __nv_bfloat16 g_ahi[(size_t)M_ * D_];
__device__ __nv_bfloat16 g_alo[(size_t)M_ * D_];
__device__ __nv_bfloat16 g_wqkvT_hi[(size_t)3 * D_ * D_];    // 6 MB
__device__ __nv_bfloat16 g_wqkvT_lo[(size_t)3 * D_ * D_];
__device__ __nv_bfloat16 g_woutT_hi[(size_t)D_ * D_];        // 2 MB
__device__ __nv_bfloat16 g_woutT_lo[(size_t)D_ * D_];

// ---------------- helpers ---------------------------------------------------
__device__ __forceinline__ uint32_t smem_u32(const void* p) {
    uint32_t a;
    asm("{ .reg .u64 t; cvta.to.shared.u64 t, %1; cvt.u32.u64 %0, t; }"
        : "=r"(a) : "l"(p));
    return a;
}
__device__ __forceinline__ void cp16(uint32_t dst, const void* src) {
    asm volatile("cp.async.cg.shared.global [%0], [%1], 16;"
                 :: "r"(dst), "l"(src) : "memory");
}
#define CP_COMMIT()  asm volatile("cp.async.commit_group;" ::: "memory")
#define CP_WAIT1()   asm volatile("cp.async.wait_group 1;" ::: "memory")
#define CP_WAIT0()   asm volatile("cp.async.wait_group 0;" ::: "memory")

#define LDSM4(r, addr) \
    asm volatile("ldmatrix.sync.aligned.m8n8.x4.shared.b16 {%0,%1,%2,%3}, [%4];" \
                 : "=r"((r)[0]), "=r"((r)[1]), "=r"((r)[2]), "=r"((r)[3]) : "r"(addr))
#define LDSM2(r, addr) \
    asm volatile("ldmatrix.sync.aligned.m8n8.x2.shared.b16 {%0,%1}, [%2];" \
                 : "=r"((r)[0]), "=r"((r)[1]) : "r"(addr))
#define LDSM2T(r, addr) \
    asm volatile("ldmatrix.sync.aligned.m8n8.x2.trans.shared.b16 {%0,%1}, [%2];" \
                 : "=r"((r)[0]), "=r"((r)[1]) : "r"(addr))
#define MMA16816(c, a, bb) \
    asm volatile("mma.sync.aligned.m16n8k16.row.col.f32.bf16.bf16.f32 " \
                 "{%0,%1,%2,%3}, {%4,%5,%6,%7}, {%8,%9}, {%0,%1,%2,%3};" \
                 : "+f"((c)[0]), "+f"((c)[1]), "+f"((c)[2]), "+f"((c)[3]) \
                 : "r"((a)[0]), "r"((a)[1]), "r"((a)[2]), "r"((a)[3]), \
                   "r"((bb)[0]), "r"((bb)[1]))

__device__ __forceinline__ void packsplit(float x, float y, uint32_t& hi, uint32_t& lo) {
    __nv_bfloat16 hx = __float2bfloat16(x), hy = __float2bfloat16(y);
    __nv_bfloat162 H = __halves2bfloat162(hx, hy);
    __nv_bfloat162 L = __halves2bfloat162(
        __float2bfloat16(x - __bfloat162float(hx)),
        __float2bfloat16(y - __bfloat162float(hy)));
    hi = *(uint32_t*)&H;
    lo = *(uint32_t*)&L;
}

// ---------------------------------------------------------------------------
// Split fp32 -> bf16 hi/lo (vectorized by 4)  [used for x only]
// ---------------------------------------------------------------------------
__global__ __launch_bounds__(256) void split_f32(
    const float4* __restrict__ in, __nv_bfloat162* __restrict__ hi,
    __nv_bfloat162* __restrict__ lo, int n4)
{
    int i = blockIdx.x * 256 + threadIdx.x;
    if (i >= n4) return;
    float4 v = in[i];
    uint32_t h0, l0, h1, l1;
    packsplit(v.x, v.y, h0, l0);
    packsplit(v.z, v.w, h1, l1);
    ((uint32_t*)hi)[2 * i + 0] = h0;
    ((uint32_t*)hi)[2 * i + 1] = h1;
    ((uint32_t*)lo)[2 * i + 0] = l0;
    ((uint32_t*)lo)[2 * i + 1] = l1;
}

// ---------------------------------------------------------------------------
// Transpose W[K][N] -> Wt[N][K] with bf16 hi/lo split
// ---------------------------------------------------------------------------
__global__ void transpose_split(
    const float* __restrict__ W, __nv_bfloat16* __restrict__ hi,
    __nv_bfloat16* __restrict__ lo, int K, int N)
{
    __shared__ float t[32][33];
    const int n0 = blockIdx.x * 32, k0 = blockIdx.y * 32;
    const int tx = threadIdx.x, ty = threadIdx.y;
#pragma unroll
    for (int j = 0; j < 32; j += 8)
        t[ty + j][tx] = W[(size_t)(k0 + ty + j) * N + n0 + tx];
    __syncthreads();
#pragma unroll
    for (int j = 0; j < 32; j += 8) {
        float v = t[tx][ty + j];
        size_t o = (size_t)(n0 + ty + j) * K + k0 + tx;
        __nv_bfloat16 h = __float2bfloat16(v);
        hi[o] = h;
        lo[o] = __float2bfloat16(v - __bfloat162float(h));
    }
}

// ---------------------------------------------------------------------------
// mma.sync bf16-split GEMM. If Chi!=null, epilogue writes bf16 hi/lo split
// instead of fp32 C.
// ---------------------------------------------------------------------------
#define GTILE 10240u                 // 128 rows * 80 B
#define GSTAGE (4u * GTILE)          // Ahi, Alo, Bhi, Blo
#define GSMEM (2u * GSTAGE)          // 81920 B

__global__ __launch_bounds__(256, 2) void gemm_bf16split_mma(
    const __nv_bfloat16* __restrict__ Ahi, const __nv_bfloat16* __restrict__ Alo,
    const __nv_bfloat16* __restrict__ Bhi, const __nv_bfloat16* __restrict__ Blo,
    const float* __restrict__ bias, float* __restrict__ C,
    __nv_bfloat16* __restrict__ Chi, __nv_bfloat16* __restrict__ Clo,
    int M, int N, int K)
{
    extern __shared__ char smem[];
    const int tid = threadIdx.x;
    const int wid = tid >> 5;
    const int lid = tid & 31;
    const int bm = blockIdx.y * 128;
    const int bn = blockIdx.x * 128;
    const int wm = (wid >> 2) * 64;
    const int wn = (wid & 3) * 32;
    const uint32_t sbase = smem_u32(smem);

    float acc[4][4][4];
#pragma unroll
    for (int i = 0; i < 4; i++)
#pragma unroll
        for (int j = 0; j < 4; j++)
#pragma unroll
            for (int c = 0; c < 4; c++) acc[i][j][c] = 0.f;

    const __nv_bfloat16* srcs[4] = {
        Ahi + (size_t)bm * K, Alo + (size_t)bm * K,
        Bhi + (size_t)bn * K, Blo + (size_t)bn * K };

    const uint32_t aRow = (uint32_t)(wm + (lid & 15)) * 80u;
    const uint32_t aCol = (uint32_t)(lid >> 4) * 16u;
    const uint32_t bRow = (uint32_t)(wn + (lid & 7)) * 80u;
    const uint32_t bCol = (uint32_t)((lid >> 3) & 1) * 16u;

    const int NIT = K >> 5;

    {
#pragma unroll
        for (int t = 0; t < 8; t++) {
            int idx = tid + (t << 8);
            int tile = idx >> 9, c = idx & 511, row = c >> 2, off = c & 3;
            uint32_t dst = sbase + (uint32_t)tile * GTILE + (uint32_t)row * 80u + (uint32_t)off * 16u;
            cp16(dst, srcs[tile] + (size_t)row * K + off * 8);
        }
        CP_COMMIT();
    }

    for (int it = 0; it < NIT; it++) {
        const uint32_t s = (uint32_t)(it & 1);
        if (it + 1 < NIT) {
            const int k0 = (it + 1) << 5;
            const uint32_t sn = (uint32_t)((it + 1) & 1);
#pragma unroll
            for (int t = 0; t < 8; t++) {
                int idx = tid + (t << 8);
                int tile = idx >> 9, c = idx & 511, row = c >> 2, off = c & 3;
                uint32_t dst = sbase + sn * GSTAGE + (uint32_t)tile * GTILE
                             + (uint32_t)row * 80u + (uint32_t)off * 16u;
                cp16(dst, srcs[tile] + (size_t)row * K + k0 + off * 8);
            }
            CP_COMMIT();
            CP_WAIT1();
        } else {
            CP_WAIT0();
        }
        __syncthreads();

        const uint32_t tb = sbase + s * GSTAGE;
#pragma unroll
        for (int kk = 0; kk < 32; kk += 16) {
            uint32_t ah[4][4], al[4][4], bh[4][2], bl[4][2];
            const uint32_t ac = (uint32_t)kk * 2u + aCol;
            const uint32_t bc = (uint32_t)kk * 2u + bCol;
#pragma unroll
            for (int mt = 0; mt < 4; mt++) {
                uint32_t ad = tb + aRow + (uint32_t)mt * 1280u + ac;
                LDSM4(ah[mt], ad);
                LDSM4(al[mt], ad + GTILE);
            }
#pragma unroll
            for (int nt = 0; nt < 4; nt++) {
                uint32_t bd = tb + 2u * GTILE + bRow + (uint32_t)nt * 640u + bc;
                LDSM2(bh[nt], bd);
                LDSM2(bl[nt], bd + GTILE);
            }
#pragma unroll
            for (int mt = 0; mt < 4; mt++)
#pragma unroll
                for (int nt = 0; nt < 4; nt++) {
                    MMA16816(acc[mt][nt], ah[mt], bh[nt]);
                    MMA16816(acc[mt][nt], ah[mt], bl[nt]);
                    MMA16816(acc[mt][nt], al[mt], bh[nt]);
                }
        }
        __syncthreads();
    }

    const int gr = lid >> 2;
    const int gc = (lid & 3) * 2;
#pragma unroll
    for (int mt = 0; mt < 4; mt++) {
#pragma unroll
        for (int nt = 0; nt < 4; nt++) {
            const int row = bm + wm + mt * 16 + gr;
            const int col = bn + wn + nt * 8 + gc;
            const float b0 = bias[col], b1 = bias[col + 1];
            float x0 = acc[mt][nt][0] + b0, x1 = acc[mt][nt][1] + b1;
            float x2 = acc[mt][nt][2] + b0, x3 = acc[mt][nt][3] + b1;
            if (Chi) {
                uint32_t h0, l0, h1, l1;
                packsplit(x0, x1, h0, l0);
                packsplit(x2, x3, h1, l1);
                size_t p0 = (size_t)row * N + col;
                size_t p1 = (size_t)(row + 8) * N + col;
                *(uint32_t*)(Chi + p0) = h0; *(uint32_t*)(Clo + p0) = l0;
                *(uint32_t*)(Chi + p1) = h1; *(uint32_t*)(Clo + p1) = l1;
            } else {
                float2 v0 = {x0, x1}, v1 = {x2, x3};
                *(float2*)&C[(size_t)row * N + col] = v0;
                *(float2*)&C[(size_t)(row + 8) * N + col] = v1;
            }
        }
    }
}

// ---------------------------------------------------------------------------
// bf16-split flash attention via mma.sync.
// Grid (T/128, B*H). 8 warps, each owns 16 query rows.
// qkv layout per row (stride 3072): q at h*64, k at 1024+h*64, v at 2048+h*64.
// S = 0.125*(Qhi Khi + Qhi Klo + Qlo Khi); P,V split the same way.
// ---------------------------------------------------------------------------
#define ARS 144u            // smem row stride bytes (72 bf16)
#define QHI_B 0u
#define QLO_B 18432u
#define KHI_B 36864u
#define KLO_B 46080u
#define VHI_B 55296u
#define VLO_B 64512u
#define MASK_B 73728u
#define ATTN_SMEM (73728 + 256)

__global__ __launch_bounds__(256, 2) void attn_mma(
    const __nv_bfloat16* __restrict__ qhi, const __nv_bfloat16* __restrict__ qlo,
    const int* __restrict__ mask,
    __nv_bfloat16* __restrict__ ohi, __nv_bfloat16* __restrict__ olo)
{
    extern __shared__ char smem[];
    int* smask = (int*)(smem + MASK_B);
    const int tid = threadIdx.x;
    const int wid = tid >> 5, lid = tid & 31;
    const int b = blockIdx.y >> 4, h = blockIdx.y & 15;
    const int q0 = blockIdx.x << 7;
    const uint32_t sb = smem_u32(smem);
    const size_t rs = 3 * D_;
    const size_t qgoff = ((size_t)(b * T_) + q0) * rs + h * DH_;
    const size_t kgoff = (size_t)(b * T_) * rs + D_ + h * DH_;
    const size_t vgoff = (size_t)(b * T_) * rs + 2 * D_ + h * DH_;
    const int* mrow = mask + b * T_;

    // prologue: async-load Q hi/lo (128 rows x 64 bf16 each)
#pragma unroll
    for (int t = 0; t < 8; t++) {
        int idx = tid + (t << 8);
        int arr = idx >> 10, c = idx & 1023, row = c >> 3, off = (c & 7) * 8;
        const __nv_bfloat16* src = (arr ? qlo : qhi) + qgoff + (size_t)row * rs + off;
        uint32_t dst = sb + (arr ? QLO_B : QHI_B) + (uint32_t)row * ARS + (uint32_t)off * 2u;
        cp16(dst, src);
    }
    CP_COMMIT();

    float s[8][4], o[8][4];
    float m0 = -1e30f, m1 = -1e30f, l0 = 0.f, l1 = 0.f;
#pragma unroll
    for (int nt = 0; nt < 8; nt++)
#pragma unroll
        for (int c = 0; c < 4; c++) o[nt][c] = 0.f;

    const uint32_t aBase = sb + QHI_B + (uint32_t)(16 * wid + (lid & 15)) * ARS
                         + (uint32_t)(lid >> 4) * 16u;
    const uint32_t kBaseRow = (uint32_t)(lid & 7) * ARS + (uint32_t)((lid >> 3) & 1) * 16u;
    const uint32_t vBaseRow = (uint32_t)(lid & 15) * ARS;

    for (int key0 = 0; key0 < T_; key0 += 64) {
        __syncthreads();   // previous tile's smem reads done
        // async-load K/V hi/lo tiles (4 arrays x 64 rows x 64 bf16)
#pragma unroll
        for (int t = 0; t < 8; t++) {
            int idx = tid + (t << 8);
            int arr = idx >> 9, c = idx & 511, row = c >> 3, off = (c & 7) * 8;
            const __nv_bfloat16* gsrc =
                (arr == 0) ? qhi + kgoff : (arr == 1) ? qlo + kgoff
              : (arr == 2) ? qhi + vgoff : qlo + vgoff;
            uint32_t darr = (arr == 0) ? KHI_B : (arr == 1) ? KLO_B
                          : (arr == 2) ? VHI_B : VLO_B;
            cp16(sb + darr + (uint32_t)row * ARS + (uint32_t)off * 2u,
                 gsrc + (size_t)(key0 + row) * rs + off);
        }
        if (tid < 64) smask[tid] = mrow[key0 + tid];
        CP_COMMIT();
        CP_WAIT0();
        __syncthreads();

        // ---- S = Q K^T (3-term split) ----
#pragma unroll
        for (int nt = 0; nt < 8; nt++)
#pragma unroll
            for (int c = 0; c < 4; c++) s[nt][c] = 0.f;
#pragma unroll
        for (int ks = 0; ks < 4; ks++) {
            uint32_t qh[4], ql[4];
            uint32_t qa = aBase + (uint32_t)ks * 32u;
            LDSM4(qh, qa);
            LDSM4(ql, qa + QLO_B);
#pragma unroll
            for (int nt = 0; nt < 8; nt++) {
                uint32_t kh[2], kl[2];
                uint32_t ka = sb + KHI_B + (uint32_t)nt * (8u * ARS) + kBaseRow
                            + (uint32_t)ks * 32u;
                LDSM2(kh, ka);
                LDSM2(kl, ka + (KLO_B - KHI_B));
                MMA16816(s[nt], qh, kh);
                MMA16816(s[nt], qh, kl);
                MMA16816(s[nt], ql, kh);
            }
        }

        // ---- scale + mask + online softmax ----
        float rm0 = -1e30f, rm1 = -1e30f;
#pragma unroll
        for (int nt = 0; nt < 8; nt++) {
            int ca = 8 * nt + 2 * (lid & 3);
            int ma = smask[ca], mb = smask[ca + 1];
            s[nt][0] = ma ? s[nt][0] * 0.125f : -1000.f;
            s[nt][2] = ma ? s[nt][2] * 0.125f : -1000.f;
            s[nt][1] = mb ? s[nt][1] * 0.125f : -1000.f;
            s[nt][3] = mb ? s[nt][3] * 0.125f : -1000.f;
            rm0 = fmaxf(rm0, fmaxf(s[nt][0], s[nt][1]));
            rm1 = fmaxf(rm1, fmaxf(s[nt][2], s[nt][3]));
        }
#pragma unroll
        for (int off = 1; off <= 2; off <<= 1) {
            rm0 = fmaxf(rm0, __shfl_xor_sync(0xffffffffu, rm0, off));
            rm1 = fmaxf(rm1, __shfl_xor_sync(0xffffffffu, rm1, off));
        }
        float mn0 = fmaxf(m0, rm0), mn1 = fmaxf(m1, rm1);
        float a0 = __expf(m0 - mn0), a1 = __expf(m1 - mn1);
        m0 = mn0; m1 = mn1;
        float rs0 = 0.f, rs1 = 0.f;
#pragma unroll
        for (int nt = 0; nt < 8; nt++) {
            s[nt][0] = __expf(s[nt][0] - mn0);
            s[nt][1] = __expf(s[nt][1] - mn0);
            s[nt][2] = __expf(s[nt][2] - mn1);
            s[nt][3] = __expf(s[nt][3] - mn1);
            rs0 += s[nt][0] + s[nt][1];
            rs1 += s[nt][2] + s[nt][3];
        }
#pragma unroll
        for (int off = 1; off <= 2; off <<= 1) {
            rs0 += __shfl_xor_sync(0xffffffffu, rs0, off);
            rs1 += __shfl_xor_sync(0xffffffffu, rs1, off);
        }
        l0 = l0 * a0 + rs0;
        l1 = l1 * a1 + rs1;
#pragma unroll
        for (int nt = 0; nt < 8; nt++) {
            o[nt][0] *= a0; o[nt][1] *= a0;
            o[nt][2] *= a1; o[nt][3] *= a1;
        }

        // ---- O += P V (3-term split; P fragments built in-register) ----
#pragma unroll
        for (int ks = 0; ks < 4; ks++) {
            uint32_t ph[4], pl[4];
            packsplit(s[2 * ks][0],     s[2 * ks][1],     ph[0], pl[0]);
            packsplit(s[2 * ks][2],     s[2 * ks][3],     ph[1], pl[1]);
            packsplit(s[2 * ks + 1][0], s[2 * ks + 1][1], ph[2], pl[2]);
            packsplit(s[2 * ks + 1][2], s[2 * ks + 1][3], ph[3], pl[3]);
#pragma unroll
            for (int nt = 0; nt < 8; nt++) {
                uint32_t vh[2], vl[2];
                uint32_t va = sb + VHI_B + (uint32_t)ks * (16u * ARS) + vBaseRow
                            + (uint32_t)nt * 16u;
                LDSM2T(vh, va);
                LDSM2T(vl, va + (VLO_B - VHI_B));
                MMA16816(o[nt], ph, vh);
                MMA16816(o[nt], ph, vl);
                MMA16816(o[nt], pl, vh);
            }
        }
    }

    // ---- finalize: write hi/lo bf16 for the out-projection ----
    float inv0 = 1.f / l0, inv1 = 1.f / l1;
    const int r0 = q0 + 16 * wid + (lid >> 2);
    const size_t base = ((size_t)(b * T_) + r0) * D_ + h * DH_ + 2 * (lid & 3);
#pragma unroll
    for (int nt = 0; nt < 8; nt++) {
        uint32_t h0, lo0, h1, lo1;
        packsplit(o[nt][0] * inv0, o[nt][1] * inv0, h0, lo0);
        packsplit(o[nt][2] * inv1, o[nt][3] * inv1, h1, lo1);
        size_t p0 = base + nt * 8;
        size_t p1 = p0 + (size_t)8 * D_;
        *(uint32_t*)(ohi + p0) = h0; *(uint32_t*)(olo + p0) = lo0;
        *(uint32_t*)(ohi + p1) = h1; *(uint32_t*)(olo + p1) = lo1;
    }
}

// ---------------------------------------------------------------------------
extern "C" void kernel_launch(void* const* d_in, const int* in_sizes, int n_in,
                              void* d_out, int out_size)
{
    (void)in_sizes; (void)n_in; (void)out_size;
    const float* x     = (const float*)d_in[0];
    const int*   mask  = (const int*)  d_in[1];
    const float* Wqkv  = (const float*)d_in[2];
    const float* bqkv  = (const float*)d_in[3];
    const float* Wout  = (const float*)d_in[4];
    const float* bout  = (const float*)d_in[5];
    float* out = (float*)d_out;

    __nv_bfloat16 *qkvhi, *qkvlo, *xhi, *xlo, *ahi, *alo, *wqh, *wql, *woh, *wol;
    cudaGetSymbolAddress((void**)&qkvhi, g_qkvhi);
    cudaGetSymbolAddress((void**)&qkvlo, g_qkvlo);
    cudaGetSymbolAddress((void**)&xhi,   g_xhi);
    cudaGetSymbolAddress((void**)&xlo,   g_xlo);
    cudaGetSymbolAddress((void**)&ahi,   g_ahi);
    cudaGetSymbolAddress((void**)&alo,   g_alo);
    cudaGetSymbolAddress((void**)&wqh,   g_wqkvT_hi);
    cudaGetSymbolAddress((void**)&wql,   g_wqkvT_lo);
    cudaGetSymbolAddress((void**)&woh,   g_woutT_hi);
    cudaGetSymbolAddress((void**)&wol,   g_woutT_lo);

    cudaFuncSetAttribute(gemm_bf16split_mma,
                         cudaFuncAttributeMaxDynamicSharedMemorySize, GSMEM);
    cudaFuncSetAttribute(attn_mma,
                         cudaFuncAttributeMaxDynamicSharedMemorySize, ATTN_SMEM);

    // split x -> bf16 hi/lo
    {
        int n4 = (M_ * D_) / 4;
        split_f32<<<(n4 + 255) / 256, 256>>>((const float4*)x,
            (__nv_bfloat162*)xhi, (__nv_bfloat162*)xlo, n4);
    }
    // transpose+split weights
    transpose_split<<<dim3((3 * D_) / 32, D_ / 32), dim3(32, 8)>>>(Wqkv, wqh, wql, D_, 3 * D_);
    transpose_split<<<dim3(D_ / 32, D_ / 32), dim3(32, 8)>>>(Wout, woh, wol, D_, D_);

    // QKV projection -> bf16 hi/lo qkv directly
    gemm_bf16split_mma<<<dim3((3 * D_) / 128, M_ / 128), 256, GSMEM>>>(
        xhi, xlo, wqh, wql, bqkv, nullptr, qkvhi, qkvlo, M_, 3 * D_, D_);

    // attention -> bf16 hi/lo output directly
    attn_mma<<<dim3(T_ / 128, B_ * H_), 256, ATTN_SMEM>>>(
        qkvhi, qkvlo, mask, ahi, alo);

    // output projection -> fp32 result
    gemm_bf16split_mma<<<dim3(D_ / 128, M_ / 128), 256, GSMEM>>>(
        ahi, alo, woh, wol, bout, out, nullptr, nullptr, M_, D_, D_);
}

// round 17
// speedup vs baseline: 3.5023x; 1.0182x over previous
#include <cuda_runtime.h>
#include <cuda_bf16.h>
#include <cstdint>
#include <math.h>

#define B_ 4
#define T_ 2048
#define D_ 1024
#define H_ 16
#define DH_ 64
#define M_ (B_ * T_)        // 8192

// ---------------- scratch (device globals; no allocs allowed) --------------
__device__ __nv_bfloat16 g_qkvhi[(size_t)M_ * 3 * D_];       // 48 MB
__device__ __nv_bfloat16 g_qkvlo[(size_t)M_ * 3 * D_];       // 48 MB
__device__ __nv_bfloat16 g_xhi[(size_t)M_ * D_];             // 16 MB
__device__ __nv_bfloat16 g_xlo[(size_t)M_ * D_];
__device__ __nv_bfloat16 g_ahi[(size_t)M_ * D_];
__device__ __nv_bfloat16 g_alo[(size_t)M_ * D_];
__device__ __nv_bfloat16 g_wqkvT_hi[(size_t)3 * D_ * D_];    // 6 MB
__device__ __nv_bfloat16 g_wqkvT_lo[(size_t)3 * D_ * D_];
__device__ __nv_bfloat16 g_woutT_hi[(size_t)D_ * D_];        // 2 MB
__device__ __nv_bfloat16 g_woutT_lo[(size_t)D_ * D_];

// ---------------- helpers ---------------------------------------------------
__device__ __forceinline__ uint32_t smem_u32(const void* p) {
    uint32_t a;
    asm("{ .reg .u64 t; cvta.to.shared.u64 t, %1; cvt.u32.u64 %0, t; }"
        : "=r"(a) : "l"(p));
    return a;
}
__device__ __forceinline__ void cp16(uint32_t dst, const void* src) {
    asm volatile("cp.async.cg.shared.global [%0], [%1], 16;"
                 :: "r"(dst), "l"(src) : "memory");
}
#define CP_COMMIT()  asm volatile("cp.async.commit_group;" ::: "memory")
#define CP_WAIT1()   asm volatile("cp.async.wait_group 1;" ::: "memory")
#define CP_WAIT0()   asm volatile("cp.async.wait_group 0;" ::: "memory")

#define LDSM4(r, addr) \
    asm volatile("ldmatrix.sync.aligned.m8n8.x4.shared.b16 {%0,%1,%2,%3}, [%4];" \
                 : "=r"((r)[0]), "=r"((r)[1]), "=r"((r)[2]), "=r"((r)[3]) : "r"(addr))
#define LDSM2(r, addr) \
    asm volatile("ldmatrix.sync.aligned.m8n8.x2.shared.b16 {%0,%1}, [%2];" \
                 : "=r"((r)[0]), "=r"((r)[1]) : "r"(addr))
#define LDSM2T(r, addr) \
    asm volatile("ldmatrix.sync.aligned.m8n8.x2.trans.shared.b16 {%0,%1}, [%2];" \
                 : "=r"((r)[0]), "=r"((r)[1]) : "r"(addr))
#define MMA16816(c, a, bb) \
    asm volatile("mma.sync.aligned.m16n8k16.row.col.f32.bf16.bf16.f32 " \
                 "{%0,%1,%2,%3}, {%4,%5,%6,%7}, {%8,%9}, {%0,%1,%2,%3};" \
                 : "+f"((c)[0]), "+f"((c)[1]), "+f"((c)[2]), "+f"((c)[3]) \
                 : "r"((a)[0]), "r"((a)[1]), "r"((a)[2]), "r"((a)[3]), \
                   "r"((bb)[0]), "r"((bb)[1]))

__device__ __forceinline__ void packsplit(float x, float y, uint32_t& hi, uint32_t& lo) {
    __nv_bfloat16 hx = __float2bfloat16(x), hy = __float2bfloat16(y);
    __nv_bfloat162 H = __halves2bfloat162(hx, hy);
    __nv_bfloat162 L = __halves2bfloat162(
        __float2bfloat16(x - __bfloat162float(hx)),
        __float2bfloat16(y - __bfloat162float(hy)));
    hi = *(uint32_t*)&H;
    lo = *(uint32_t*)&L;
}

// ---------------------------------------------------------------------------
// Split fp32 -> bf16 hi/lo (vectorized by 4)  [used for x only]
// ---------------------------------------------------------------------------
__global__ __launch_bounds__(256) void split_f32(
    const float4* __restrict__ in, __nv_bfloat162* __restrict__ hi,
    __nv_bfloat162* __restrict__ lo, int n4)
{
    int i = blockIdx.x * 256 + threadIdx.x;
    if (i >= n4) return;
    float4 v = in[i];
    uint32_t h0, l0, h1, l1;
    packsplit(v.x, v.y, h0, l0);
    packsplit(v.z, v.w, h1, l1);
    ((uint32_t*)hi)[2 * i + 0] = h0;
    ((uint32_t*)hi)[2 * i + 1] = h1;
    ((uint32_t*)lo)[2 * i + 0] = l0;
    ((uint32_t*)lo)[2 * i + 1] = l1;
}

// ---------------------------------------------------------------------------
// Transpose W[K][N] -> Wt[N][K] with bf16 hi/lo split
// ---------------------------------------------------------------------------
__global__ void transpose_split(
    const float* __restrict__ W, __nv_bfloat16* __restrict__ hi,
    __nv_bfloat16* __restrict__ lo, int K, int N)
{
    __shared__ float t[32][33];
    const int n0 = blockIdx.x * 32, k0 = blockIdx.y * 32;
    const int tx = threadIdx.x, ty = threadIdx.y;
#pragma unroll
    for (int j = 0; j < 32; j += 8)
        t[ty + j][tx] = W[(size_t)(k0 + ty + j) * N + n0 + tx];
    __syncthreads();
#pragma unroll
    for (int j = 0; j < 32; j += 8) {
        float v = t[tx][ty + j];
        size_t o = (size_t)(n0 + ty + j) * K + k0 + tx;
        __nv_bfloat16 h = __float2bfloat16(v);
        hi[o] = h;
        lo[o] = __float2bfloat16(v - __bfloat162float(h));
    }
}

// ---------------------------------------------------------------------------
// mma.sync bf16-split GEMM. If Chi!=null, epilogue writes bf16 hi/lo split
// instead of fp32 C.  (unchanged from R16 passing version)
// ---------------------------------------------------------------------------
#define GTILE 10240u                 // 128 rows * 80 B
#define GSTAGE (4u * GTILE)          // Ahi, Alo, Bhi, Blo
#define GSMEM (2u * GSTAGE)          // 81920 B

__global__ __launch_bounds__(256, 2) void gemm_bf16split_mma(
    const __nv_bfloat16* __restrict__ Ahi, const __nv_bfloat16* __restrict__ Alo,
    const __nv_bfloat16* __restrict__ Bhi, const __nv_bfloat16* __restrict__ Blo,
    const float* __restrict__ bias, float* __restrict__ C,
    __nv_bfloat16* __restrict__ Chi, __nv_bfloat16* __restrict__ Clo,
    int M, int N, int K)
{
    extern __shared__ char smem[];
    const int tid = threadIdx.x;
    const int wid = tid >> 5;
    const int lid = tid & 31;
    const int bm = blockIdx.y * 128;
    const int bn = blockIdx.x * 128;
    const int wm = (wid >> 2) * 64;
    const int wn = (wid & 3) * 32;
    const uint32_t sbase = smem_u32(smem);

    float acc[4][4][4];
#pragma unroll
    for (int i = 0; i < 4; i++)
#pragma unroll
        for (int j = 0; j < 4; j++)
#pragma unroll
            for (int c = 0; c < 4; c++) acc[i][j][c] = 0.f;

    const __nv_bfloat16* srcs[4] = {
        Ahi + (size_t)bm * K, Alo + (size_t)bm * K,
        Bhi + (size_t)bn * K, Blo + (size_t)bn * K };

    const uint32_t aRow = (uint32_t)(wm + (lid & 15)) * 80u;
    const uint32_t aCol = (uint32_t)(lid >> 4) * 16u;
    const uint32_t bRow = (uint32_t)(wn + (lid & 7)) * 80u;
    const uint32_t bCol = (uint32_t)((lid >> 3) & 1) * 16u;

    const int NIT = K >> 5;

    {
#pragma unroll
        for (int t = 0; t < 8; t++) {
            int idx = tid + (t << 8);
            int tile = idx >> 9, c = idx & 511, row = c >> 2, off = c & 3;
            uint32_t dst = sbase + (uint32_t)tile * GTILE + (uint32_t)row * 80u + (uint32_t)off * 16u;
            cp16(dst, srcs[tile] + (size_t)row * K + off * 8);
        }
        CP_COMMIT();
    }

    for (int it = 0; it < NIT; it++) {
        const uint32_t s = (uint32_t)(it & 1);
        if (it + 1 < NIT) {
            const int k0 = (it + 1) << 5;
            const uint32_t sn = (uint32_t)((it + 1) & 1);
#pragma unroll
            for (int t = 0; t < 8; t++) {
                int idx = tid + (t << 8);
                int tile = idx >> 9, c = idx & 511, row = c >> 2, off = c & 3;
                uint32_t dst = sbase + sn * GSTAGE + (uint32_t)tile * GTILE
                             + (uint32_t)row * 80u + (uint32_t)off * 16u;
                cp16(dst, srcs[tile] + (size_t)row * K + k0 + off * 8);
            }
            CP_COMMIT();
            CP_WAIT1();
        } else {
            CP_WAIT0();
        }
        __syncthreads();

        const uint32_t tb = sbase + s * GSTAGE;
#pragma unroll
        for (int kk = 0; kk < 32; kk += 16) {
            uint32_t ah[4][4], al[4][4], bh[4][2], bl[4][2];
            const uint32_t ac = (uint32_t)kk * 2u + aCol;
            const uint32_t bc = (uint32_t)kk * 2u + bCol;
#pragma unroll
            for (int mt = 0; mt < 4; mt++) {
                uint32_t ad = tb + aRow + (uint32_t)mt * 1280u + ac;
                LDSM4(ah[mt], ad);
                LDSM4(al[mt], ad + GTILE);
            }
#pragma unroll
            for (int nt = 0; nt < 4; nt++) {
                uint32_t bd = tb + 2u * GTILE + bRow + (uint32_t)nt * 640u + bc;
                LDSM2(bh[nt], bd);
                LDSM2(bl[nt], bd + GTILE);
            }
#pragma unroll
            for (int mt = 0; mt < 4; mt++)
#pragma unroll
                for (int nt = 0; nt < 4; nt++) {
                    MMA16816(acc[mt][nt], ah[mt], bh[nt]);
                    MMA16816(acc[mt][nt], ah[mt], bl[nt]);
                    MMA16816(acc[mt][nt], al[mt], bh[nt]);
                }
        }
        __syncthreads();
    }

    const int gr = lid >> 2;
    const int gc = (lid & 3) * 2;
#pragma unroll
    for (int mt = 0; mt < 4; mt++) {
#pragma unroll
        for (int nt = 0; nt < 4; nt++) {
            const int row = bm + wm + mt * 16 + gr;
            const int col = bn + wn + nt * 8 + gc;
            const float b0 = bias[col], b1 = bias[col + 1];
            float x0 = acc[mt][nt][0] + b0, x1 = acc[mt][nt][1] + b1;
            float x2 = acc[mt][nt][2] + b0, x3 = acc[mt][nt][3] + b1;
            if (Chi) {
                uint32_t h0, l0, h1, l1;
                packsplit(x0, x1, h0, l0);
                packsplit(x2, x3, h1, l1);
                size_t p0 = (size_t)row * N + col;
                size_t p1 = (size_t)(row + 8) * N + col;
                *(uint32_t*)(Chi + p0) = h0; *(uint32_t*)(Clo + p0) = l0;
                *(uint32_t*)(Chi + p1) = h1; *(uint32_t*)(Clo + p1) = l1;
            } else {
                float2 v0 = {x0, x1}, v1 = {x2, x3};
                *(float2*)&C[(size_t)row * N + col] = v0;
                *(float2*)&C[(size_t)(row + 8) * N + col] = v1;
            }
        }
    }
}

// ---------------------------------------------------------------------------
// bf16-split flash attention via mma.sync — NOW with 2-stage K/V pipeline.
// Grid (T/128, B*H). 8 warps, each owns 16 query rows.
// Smem: Q hi/lo (36864) + 2 stages of K/V hi/lo (36864 each) + mask (2x256).
// ---------------------------------------------------------------------------
#define ARS 144u            // smem row stride bytes (72 bf16)
#define QHI_B 0u
#define QLO_B 18432u
#define STG0_B 36864u
#define STG_SZ 36864u       // KHI(0) KLO(9216) VHI(18432) VLO(27648)
#define MASK_B 110592u      // 2 stages x 64 ints
#define ATTN_SMEM (110592 + 512)

__global__ __launch_bounds__(256, 2) void attn_mma(
    const __nv_bfloat16* __restrict__ qhi, const __nv_bfloat16* __restrict__ qlo,
    const int* __restrict__ mask,
    __nv_bfloat16* __restrict__ ohi, __nv_bfloat16* __restrict__ olo)
{
    extern __shared__ char smem[];
    int* smask = (int*)(smem + MASK_B);
    const int tid = threadIdx.x;
    const int wid = tid >> 5, lid = tid & 31;
    const int b = blockIdx.y >> 4, h = blockIdx.y & 15;
    const int q0 = blockIdx.x << 7;
    const uint32_t sb = smem_u32(smem);
    const size_t rs = 3 * D_;
    const size_t qgoff = ((size_t)(b * T_) + q0) * rs + h * DH_;
    const size_t kgoff = (size_t)(b * T_) * rs + D_ + h * DH_;
    const size_t vgoff = (size_t)(b * T_) * rs + 2 * D_ + h * DH_;
    const int* mrow = mask + b * T_;

    // prologue: async-load Q hi/lo (128 rows x 64 bf16 each)
#pragma unroll
    for (int t = 0; t < 8; t++) {
        int idx = tid + (t << 8);
        int arr = idx >> 10, c = idx & 1023, row = c >> 3, off = (c & 7) * 8;
        const __nv_bfloat16* src = (arr ? qlo : qhi) + qgoff + (size_t)row * rs + off;
        uint32_t dst = sb + (arr ? QLO_B : QHI_B) + (uint32_t)row * ARS + (uint32_t)off * 2u;
        cp16(dst, src);
    }
    CP_COMMIT();

    // prologue: tile 0 -> stage 0
    {
#pragma unroll
        for (int t = 0; t < 8; t++) {
            int idx = tid + (t << 8);
            int arr = idx >> 9, c = idx & 511, row = c >> 3, off = (c & 7) * 8;
            const __nv_bfloat16* gsrc =
                (arr == 0) ? qhi + kgoff : (arr == 1) ? qlo + kgoff
              : (arr == 2) ? qhi + vgoff : qlo + vgoff;
            cp16(sb + STG0_B + (uint32_t)arr * 9216u + (uint32_t)row * ARS + (uint32_t)off * 2u,
                 gsrc + (size_t)row * rs + off);
        }
        if (tid < 64) smask[tid] = mrow[tid];
        CP_COMMIT();
    }

    float s[8][4], o[8][4];
    float m0 = -1e30f, m1 = -1e30f, l0 = 0.f, l1 = 0.f;
#pragma unroll
    for (int nt = 0; nt < 8; nt++)
#pragma unroll
        for (int c = 0; c < 4; c++) o[nt][c] = 0.f;

    const uint32_t aBase = sb + QHI_B + (uint32_t)(16 * wid + (lid & 15)) * ARS
                         + (uint32_t)(lid >> 4) * 16u;
    const uint32_t kBaseRow = (uint32_t)(lid & 7) * ARS + (uint32_t)((lid >> 3) & 1) * 16u;
    const uint32_t vBaseRow = (uint32_t)(lid & 15) * ARS;

    const int NT = T_ / 64;   // 32
    for (int it = 0; it < NT; it++) {
        const uint32_t stg = sb + STG0_B + (uint32_t)(it & 1) * STG_SZ;

        // issue next tile into the other stage (overlaps this tile's compute wait)
        if (it + 1 < NT) {
            const int key0n = (it + 1) << 6;
            const uint32_t stgn = sb + STG0_B + (uint32_t)((it + 1) & 1) * STG_SZ;
#pragma unroll
            for (int t = 0; t < 8; t++) {
                int idx = tid + (t << 8);
                int arr = idx >> 9, c = idx & 511, row = c >> 3, off = (c & 7) * 8;
                const __nv_bfloat16* gsrc =
                    (arr == 0) ? qhi + kgoff : (arr == 1) ? qlo + kgoff
                  : (arr == 2) ? qhi + vgoff : qlo + vgoff;
                cp16(stgn + (uint32_t)arr * 9216u + (uint32_t)row * ARS + (uint32_t)off * 2u,
                     gsrc + (size_t)(key0n + row) * rs + off);
            }
            if (tid < 64) smask[((it + 1) & 1) * 64 + tid] = mrow[key0n + tid];
            CP_COMMIT();
            CP_WAIT1();           // Q + tile it complete; tile it+1 in flight
        } else {
            CP_WAIT0();
        }
        __syncthreads();

        const int* smk = smask + (it & 1) * 64;

        // ---- S = Q K^T (3-term split) ----
#pragma unroll
        for (int nt = 0; nt < 8; nt++)
#pragma unroll
            for (int c = 0; c < 4; c++) s[nt][c] = 0.f;
#pragma unroll
        for (int ks = 0; ks < 4; ks++) {
            uint32_t qh[4], ql[4];
            uint32_t qa = aBase + (uint32_t)ks * 32u;
            LDSM4(qh, qa);
            LDSM4(ql, qa + QLO_B);
#pragma unroll
            for (int nt = 0; nt < 8; nt++) {
                uint32_t kh[2], kl[2];
                uint32_t ka = stg + (uint32_t)nt * (8u * ARS) + kBaseRow
                            + (uint32_t)ks * 32u;
                LDSM2(kh, ka);
                LDSM2(kl, ka + 9216u);
                MMA16816(s[nt], qh, kh);
                MMA16816(s[nt], qh, kl);
                MMA16816(s[nt], ql, kh);
            }
        }

        // ---- scale + mask + online softmax ----
        float rm0 = -1e30f, rm1 = -1e30f;
#pragma unroll
        for (int nt = 0; nt < 8; nt++) {
            int ca = 8 * nt + 2 * (lid & 3);
            int ma = smk[ca], mb = smk[ca + 1];
            s[nt][0] = ma ? s[nt][0] * 0.125f : -1000.f;
            s[nt][2] = ma ? s[nt][2] * 0.125f : -1000.f;
            s[nt][1] = mb ? s[nt][1] * 0.125f : -1000.f;
            s[nt][3] = mb ? s[nt][3] * 0.125f : -1000.f;
            rm0 = fmaxf(rm0, fmaxf(s[nt][0], s[nt][1]));
            rm1 = fmaxf(rm1, fmaxf(s[nt][2], s[nt][3]));
        }
#pragma unroll
        for (int off = 1; off <= 2; off <<= 1) {
            rm0 = fmaxf(rm0, __shfl_xor_sync(0xffffffffu, rm0, off));
            rm1 = fmaxf(rm1, __shfl_xor_sync(0xffffffffu, rm1, off));
        }
        float mn0 = fmaxf(m0, rm0), mn1 = fmaxf(m1, rm1);
        float a0 = __expf(m0 - mn0), a1 = __expf(m1 - mn1);
        m0 = mn0; m1 = mn1;
        float rs0 = 0.f, rs1 = 0.f;
#pragma unroll
        for (int nt = 0; nt < 8; nt++) {
            s[nt][0] = __expf(s[nt][0] - mn0);
            s[nt][1] = __expf(s[nt][1] - mn0);
            s[nt][2] = __expf(s[nt][2] - mn1);
            s[nt][3] = __expf(s[nt][3] - mn1);
            rs0 += s[nt][0] + s[nt][1];
            rs1 += s[nt][2] + s[nt][3];
        }
#pragma unroll
        for (int off = 1; off <= 2; off <<= 1) {
            rs0 += __shfl_xor_sync(0xffffffffu, rs0, off);
            rs1 += __shfl_xor_sync(0xffffffffu, rs1, off);
        }
        l0 = l0 * a0 + rs0;
        l1 = l1 * a1 + rs1;
#pragma unroll
        for (int nt = 0; nt < 8; nt++) {
            o[nt][0] *= a0; o[nt][1] *= a0;
            o[nt][2] *= a1; o[nt][3] *= a1;
        }

        // ---- O += P V (3-term split; P fragments built in-register) ----
#pragma unroll
        for (int ks = 0; ks < 4; ks++) {
            uint32_t ph[4], pl[4];
            packsplit(s[2 * ks][0],     s[2 * ks][1],     ph[0], pl[0]);
            packsplit(s[2 * ks][2],     s[2 * ks][3],     ph[1], pl[1]);
            packsplit(s[2 * ks + 1][0], s[2 * ks + 1][1], ph[2], pl[2]);
            packsplit(s[2 * ks + 1][2], s[2 * ks + 1][3], ph[3], pl[3]);
#pragma unroll
            for (int nt = 0; nt < 8; nt++) {
                uint32_t vh[2], vl[2];
                uint32_t va = stg + 18432u + (uint32_t)ks * (16u * ARS) + vBaseRow
                            + (uint32_t)nt * 16u;
                LDSM2T(vh, va);
                LDSM2T(vl, va + 9216u);
                MMA16816(o[nt], ph, vh);
                MMA16816(o[nt], ph, vl);
                MMA16816(o[nt], pl, vh);
            }
        }
        __syncthreads();   // protect this stage before next iter's cp.async reuses it
    }

    // ---- finalize: write hi/lo bf16 for the out-projection ----
    float inv0 = 1.f / l0, inv1 = 1.f / l1;
    const int r0 = q0 + 16 * wid + (lid >> 2);
    const size_t base = ((size_t)(b * T_) + r0) * D_ + h * DH_ + 2 * (lid & 3);
#pragma unroll
    for (int nt = 0; nt < 8; nt++) {
        uint32_t h0, lo0, h1, lo1;
        packsplit(o[nt][0] * inv0, o[nt][1] * inv0, h0, lo0);
        packsplit(o[nt][2] * inv1, o[nt][3] * inv1, h1, lo1);
        size_t p0 = base + nt * 8;
        size_t p1 = p0 + (size_t)8 * D_;
        *(uint32_t*)(ohi + p0) = h0; *(uint32_t*)(olo + p0) = lo0;
        *(uint32_t*)(ohi + p1) = h1; *(uint32_t*)(olo + p1) = lo1;
    }
}

// ---------------------------------------------------------------------------
extern "C" void kernel_launch(void* const* d_in, const int* in_sizes, int n_in,
                              void* d_out, int out_size)
{
    (void)in_sizes; (void)n_in; (void)out_size;
    const float* x     = (const float*)d_in[0];
    const int*   mask  = (const int*)  d_in[1];
    const float* Wqkv  = (const float*)d_in[2];
    const float* bqkv  = (const float*)d_in[3];
    const float* Wout  = (const float*)d_in[4];
    const float* bout  = (const float*)d_in[5];
    float* out = (float*)d_out;

    __nv_bfloat16 *qkvhi, *qkvlo, *xhi, *xlo, *ahi, *alo, *wqh, *wql, *woh, *wol;
    cudaGetSymbolAddress((void**)&qkvhi, g_qkvhi);
    cudaGetSymbolAddress((void**)&qkvlo, g_qkvlo);
    cudaGetSymbolAddress((void**)&xhi,   g_xhi);
    cudaGetSymbolAddress((void**)&xlo,   g_xlo);
    cudaGetSymbolAddress((void**)&ahi,   g_ahi);
    cudaGetSymbolAddress((void**)&alo,   g_alo);
    cudaGetSymbolAddress((void**)&wqh,   g_wqkvT_hi);
    cudaGetSymbolAddress((void**)&wql,   g_wqkvT_lo);
    cudaGetSymbolAddress((void**)&woh,   g_woutT_hi);
    cudaGetSymbolAddress((void**)&wol,   g_woutT_lo);

    cudaFuncSetAttribute(gemm_bf16split_mma,
                         cudaFuncAttributeMaxDynamicSharedMemorySize, GSMEM);
    cudaFuncSetAttribute(attn_mma,
                         cudaFuncAttributeMaxDynamicSharedMemorySize, ATTN_SMEM);

    // split x -> bf16 hi/lo
    {
        int n4 = (M_ * D_) / 4;
        split_f32<<<(n4 + 255) / 256, 256>>>((const float4*)x,
            (__nv_bfloat162*)xhi, (__nv_bfloat162*)xlo, n4);
    }
    // transpose+split weights
    transpose_split<<<dim3((3 * D_) / 32, D_ / 32), dim3(32, 8)>>>(Wqkv, wqh, wql, D_, 3 * D_);
    transpose_split<<<dim3(D_ / 32, D_ / 32), dim3(32, 8)>>>(Wout, woh, wol, D_, D_);

    // QKV projection -> bf16 hi/lo qkv directly
    gemm_bf16split_mma<<<dim3((3 * D_) / 128, M_ / 128), 256, GSMEM>>>(
        xhi, xlo, wqh, wql, bqkv, nullptr, qkvhi, qkvlo, M_, 3 * D_, D_);

    // attention -> bf16 hi/lo output directly
    attn_mma<<<dim3(T_ / 128, B_ * H_), 256, ATTN_SMEM>>>(
        qkvhi, qkvlo, mask, ahi, alo);

    // output projection -> fp32 result
    gemm_bf16split_mma<<<dim3(D_ / 128, M_ / 128), 256, GSMEM>>>(
        ahi, alo, woh, wol, bout, out, nullptr, nullptr, M_, D_, D_);
}